// round 16
// baseline (speedup 1.0000x reference)
#include <cuda_runtime.h>
#include <cuda_fp16.h>
#include <cstdint>

#define BATCH 4
#define CIN   256
#define DIM   64
#define HWDIM 64
#define NPIX  4096
#define LN_EPS 1e-5f

// ---------------- scratch (device globals; no allocation allowed) ----------
__device__ float g_att[BATCH * DIM * NPIX];   // inner projection out [b][d][n]
__device__ float g_ao [BATCH * DIM * NPIX];   // attention out [b][d][n]
__device__ float g_wt [DIM * CIN];            // w_out transposed [d][c]

// fp16 hi/lo staging, PRE-SWIZZLED (SW128-style) 8KB tiles (64x64 halfs):
// Q: tile it=n>>6, byte sw128((n&63)*128 + d*2)   [row][d]
// K: tile jt=n>>6, byte sw128((n&63)*128 + d*2)   [key][d]
// V: tile jt=n>>6, byte sw128(d*128 + (n&63)*2)   [d][key]
__device__ __align__(16) unsigned char g_qh8[BATCH * 64 * 8192];
__device__ __align__(16) unsigned char g_ql8[BATCH * 64 * 8192];
__device__ __align__(16) unsigned char g_kh8[BATCH * 64 * 8192];
__device__ __align__(16) unsigned char g_kl8[BATCH * 64 * 8192];
__device__ __align__(16) unsigned char g_vh8[BATCH * 64 * 8192];
__device__ __align__(16) unsigned char g_vl8[BATCH * 64 * 8192];

// ---------------- helpers --------------------------------------------------
__device__ __forceinline__ uint32_t smem_u32(const void* p) {
    uint32_t a;
    asm("{ .reg .u64 t; cvta.to.shared.u64 t, %1; cvt.u32.u64 %0, t; }"
        : "=r"(a) : "l"(p));
    return a;
}
__device__ __forceinline__ uint32_t sw128(uint32_t off) {
    return off ^ ((off >> 3) & 0x70);
}
__device__ __forceinline__ void ldsm4(uint32_t& r0, uint32_t& r1,
                                      uint32_t& r2, uint32_t& r3, uint32_t addr) {
    asm volatile("ldmatrix.sync.aligned.m8n8.x4.shared.b16 {%0,%1,%2,%3}, [%4];"
        : "=r"(r0), "=r"(r1), "=r"(r2), "=r"(r3) : "r"(addr));
}
__device__ __forceinline__ void mma16816(float* d, const uint32_t* a,
                                         uint32_t b0, uint32_t b1) {
    asm volatile(
        "mma.sync.aligned.m16n8k16.row.col.f32.f16.f16.f32 "
        "{%0,%1,%2,%3}, {%4,%5,%6,%7}, {%8,%9}, {%0,%1,%2,%3};"
        : "+f"(d[0]), "+f"(d[1]), "+f"(d[2]), "+f"(d[3])
        : "r"(a[0]), "r"(a[1]), "r"(a[2]), "r"(a[3]), "r"(b0), "r"(b1));
}
__device__ __forceinline__ uint32_t hpack(__half a, __half b) {
    return (uint32_t)__half_as_ushort(a) | ((uint32_t)__half_as_ushort(b) << 16);
}

// O += P * V for one key-chunk set (hi/lo, ll dropped). Used in-loop and flush.
__device__ __forceinline__ void pv_gemm(float O[8][4],
                                        const uint32_t pah[4][4],
                                        const uint32_t pal[4][4],
                                        uint32_t vbH, uint32_t vbL,
                                        int brow, int bcol) {
    #pragma unroll
    for (int kc2 = 0; kc2 < 4; kc2++) {
        #pragma unroll
        for (int dp = 0; dp < 4; dp++) {
            uint32_t off = sw128(
                (uint32_t)((16 * dp + brow) * 128 + (kc2 * 16 + bcol) * 2));
            uint32_t v0, v1, v2, v3;
            ldsm4(v0, v1, v2, v3, vbH + off);
            mma16816(O[2 * dp],     pah[kc2], v0, v1);
            mma16816(O[2 * dp + 1], pah[kc2], v2, v3);
            mma16816(O[2 * dp],     pal[kc2], v0, v1);
            mma16816(O[2 * dp + 1], pal[kc2], v2, v3);
            ldsm4(v0, v1, v2, v3, vbL + off);
            mma16816(O[2 * dp],     pah[kc2], v0, v1);
            mma16816(O[2 * dp + 1], pah[kc2], v2, v3);
        }
    }
}

// ============================================================================
// Kernel 0: transpose w_out [c][d] -> g_wt [d][c]
// ============================================================================
__global__ __launch_bounds__(256) void k_transpose_w(const float* __restrict__ w_out)
{
    g_wt[blockIdx.x * CIN + threadIdx.x] = w_out[threadIdx.x * DIM + blockIdx.x];
}

// ============================================================================
// Kernel 1: 1x1 in-projection (plain FFMA, proven)
// ============================================================================
__global__ __launch_bounds__(256) void k_proj_in(
    const float* __restrict__ x, const float* __restrict__ w,
    const float* __restrict__ bias)
{
    __shared__ float ws[32 * 68];
    __shared__ float xs[32 * 68];
    const int b   = blockIdx.y;
    const int n0  = blockIdx.x * 64;
    const int tid = threadIdx.x;
    const int ti  = tid >> 4;
    const int tj  = tid & 15;

    float acc[4][4] = {};
    for (int c0 = 0; c0 < CIN; c0 += 32) {
        __syncthreads();
        #pragma unroll
        for (int t = 0; t < 8; t++) {
            int idx = tid + t * 256;
            int d = idx >> 5, ci = idx & 31;
            ws[ci * 68 + d] = w[d * CIN + c0 + ci];
        }
        #pragma unroll
        for (int t = 0; t < 2; t++) {
            int idx4 = tid + t * 256;
            int ci = idx4 >> 4, p4 = idx4 & 15;
            float4 v = *(const float4*)&x[((b * CIN) + c0 + ci) * NPIX + n0 + p4 * 4];
            *(float4*)&xs[ci * 68 + p4 * 4] = v;
        }
        __syncthreads();
        #pragma unroll
        for (int ci = 0; ci < 32; ci++) {
            float4 a4 = *(const float4*)&ws[ci * 68 + 4 * ti];
            float4 b4 = *(const float4*)&xs[ci * 68 + 4 * tj];
            acc[0][0] += a4.x * b4.x; acc[0][1] += a4.x * b4.y;
            acc[0][2] += a4.x * b4.z; acc[0][3] += a4.x * b4.w;
            acc[1][0] += a4.y * b4.x; acc[1][1] += a4.y * b4.y;
            acc[1][2] += a4.y * b4.z; acc[1][3] += a4.y * b4.w;
            acc[2][0] += a4.z * b4.x; acc[2][1] += a4.z * b4.y;
            acc[2][2] += a4.z * b4.z; acc[2][3] += a4.z * b4.w;
            acc[3][0] += a4.w * b4.x; acc[3][1] += a4.w * b4.y;
            acc[3][2] += a4.w * b4.z; acc[3][3] += a4.w * b4.w;
        }
    }
    #pragma unroll
    for (int di = 0; di < 4; di++) {
        int d = 4 * ti + di;
        float bb = bias[d];
        float4 o = make_float4(acc[di][0] + bb, acc[di][1] + bb,
                               acc[di][2] + bb, acc[di][3] + bb);
        *(float4*)&g_att[((b * DIM) + d) * NPIX + n0 + 4 * tj] = o;
    }
}

// ============================================================================
// Kernel 2: 3x3 conv (pad 1) -> fp16 hi/lo pre-swizzled 64x64 tiles
// ============================================================================
__global__ __launch_bounds__(256) void k_qkv(
    const float* __restrict__ wq, const float* __restrict__ bq,
    const float* __restrict__ wk, const float* __restrict__ bk,
    const float* __restrict__ wv, const float* __restrict__ bv)
{
    __shared__ float att_s[DIM * 100];
    __shared__ float ws[8 * 64 * 9];

    const int b = blockIdx.y;
    const int z = blockIdx.z;
    const float* w    = (z == 0) ? wq : (z == 1) ? wk : wv;
    const float* bias = (z == 0) ? bq : (z == 1) ? bk : bv;

    const int tile = blockIdx.x;
    const int th = (tile >> 3) * 8, tw = (tile & 7) * 8;
    const int tid = threadIdx.x;

    for (int idx = tid; idx < DIM * 100; idx += 256) {
        int c = idx / 100, rem = idx - c * 100;
        int r = rem / 10, cc = rem - r * 10;
        int gh = th - 1 + r, gw = tw - 1 + cc;
        float v = 0.f;
        if (gh >= 0 && gh < HWDIM && gw >= 0 && gw < HWDIM)
            v = g_att[((b * DIM) + c) * NPIX + gh * HWDIM + gw];
        att_s[idx] = v;
    }

    const int d  = tid & 63;
    const int sub = tid >> 6;
    const int sy = (sub >> 1) * 4, sx = (sub & 1) * 4;
    float acc[16] = {};

    for (int c8 = 0; c8 < 8; c8++) {
        __syncthreads();
        #pragma unroll
        for (int t = 0; t < 18; t++) {
            int idx = tid + t * 256;
            int ci = idx / 576, rem2 = idx - ci * 576;
            int dd = rem2 / 9, k = rem2 - dd * 9;
            ws[idx] = w[(dd * DIM + c8 * 8 + ci) * 9 + k];
        }
        __syncthreads();
        #pragma unroll
        for (int ci = 0; ci < 8; ci++) {
            int c = c8 * 8 + ci;
            float patch[36];
            #pragma unroll
            for (int ry = 0; ry < 6; ry++)
                #pragma unroll
                for (int rx = 0; rx < 6; rx++)
                    patch[ry * 6 + rx] = att_s[c * 100 + (sy + ry) * 10 + sx + rx];
            const float* wp = &ws[(ci * 64 + d) * 9];
            float w9[9];
            #pragma unroll
            for (int k = 0; k < 9; k++) w9[k] = wp[k];
            #pragma unroll
            for (int py = 0; py < 4; py++)
                #pragma unroll
                for (int px = 0; px < 4; px++) {
                    float a = acc[py * 4 + px];
                    #pragma unroll
                    for (int ky = 0; ky < 3; ky++)
                        #pragma unroll
                        for (int kx = 0; kx < 3; kx++)
                            a += w9[ky * 3 + kx] * patch[(py + ky) * 6 + px + kx];
                    acc[py * 4 + px] = a;
                }
        }
    }

    const float bb = bias[d];
    #pragma unroll
    for (int py = 0; py < 4; py++)
        #pragma unroll
        for (int px = 0; px < 4; px++) {
            float val = acc[py * 4 + px] + bb;
            int n = (th + sy + py) * HWDIM + tw + sx + px;
            __half hi = __float2half_rn(val);
            __half lo = __float2half_rn(val - __half2float(hi));
            int t = n >> 6, r = n & 63;
            size_t tbase = ((size_t)(b * 64 + t)) * 8192;
            if (z == 0) {
                uint32_t off = sw128((uint32_t)(r * 128 + d * 2));
                *(__half*)(g_qh8 + tbase + off) = hi;
                *(__half*)(g_ql8 + tbase + off) = lo;
            } else if (z == 1) {
                uint32_t off = sw128((uint32_t)(r * 128 + d * 2));
                *(__half*)(g_kh8 + tbase + off) = hi;
                *(__half*)(g_kl8 + tbase + off) = lo;
            } else {
                uint32_t off = sw128((uint32_t)(d * 128 + r * 2));
                *(__half*)(g_vh8 + tbase + off) = hi;
                *(__half*)(g_vl8 + tbase + off) = lo;
            }
        }
}

// ============================================================================
// Kernel 3: flash attention via mma.sync (fp16 hi/lo, f32 accumulate).
// DEFERRED-PV PINGPONG: at iter j, issue S_j MMAs, then O += P_{j-1} V_{j-1}
// MMAs (independent), then softmax_j overlaps the O-GEMM drain.
//   O'_j = (O'_{j-1} + P_{j-1} V_{j-1}) * sc_j ; final flush adds P_63 V_63.
// K single-buffered, V double-buffered (V_{j-1} must survive iter j).
// Q stages through the V buffers before the loop. 48KB static smem.
// ============================================================================
__global__ __launch_bounds__(128) void k_flash_mma()
{
    __shared__ __align__(128) __half KH[4096], KL[4096];
    __shared__ __align__(128) __half VH[2][4096], VL[2][4096];

    const int tid = threadIdx.x;
    const int w   = tid >> 5;
    const int l   = tid & 31;
    const int b   = blockIdx.y;
    const int it  = blockIdx.x;

    // ---- stage Q tile (hi/lo) through V buffers ----
    {
        const float4* sh = (const float4*)(g_qh8 + ((size_t)(b * 64 + it)) * 8192);
        const float4* sl = (const float4*)(g_ql8 + ((size_t)(b * 64 + it)) * 8192);
        #pragma unroll
        for (int t = 0; t < 4; t++) {
            ((float4*)VH[0])[tid + t * 128] = sh[tid + t * 128];
            ((float4*)VL[0])[tid + t * 128] = sl[tid + t * 128];
        }
    }
    __syncthreads();

    // ---- persistent Q A-frags (4 k-chunks x hi/lo) ----
    uint32_t qh[4][4], ql[4][4];
    {
        const uint32_t qbH = smem_u32(VH[0]), qbL = smem_u32(VL[0]);
        int row  = 16 * w + (l & 15);
        int colb = (l >> 4) << 3;
        #pragma unroll
        for (int kc = 0; kc < 4; kc++) {
            uint32_t off = sw128((uint32_t)(row * 128 + (kc * 16 + colb) * 2));
            ldsm4(qh[kc][0], qh[kc][1], qh[kc][2], qh[kc][3], qbH + off);
            ldsm4(ql[kc][0], ql[kc][1], ql[kc][2], ql[kc][3], qbL + off);
        }
    }

    const uint32_t kbH = smem_u32(KH), kbL = smem_u32(KL);
    const int brow = ((l >> 4) << 3) + (l & 7);
    const int bcol = (l & 8);

    float O[8][4];
    #pragma unroll
    for (int t = 0; t < 8; t++)
        #pragma unroll
        for (int k = 0; k < 4; k++) O[t][k] = 0.f;
    float m0 = -1e30f, m1 = -1e30f, l0 = 0.f, l1 = 0.f;
    uint32_t pah[4][4], pal[4][4];   // loop-carried P frags

    for (int jt = 0; jt < 64; jt++) {
        const int s = jt & 1;
        __syncthreads();   // prior iter's ldsm reads of K and V[s] done
        {
            size_t gb = ((size_t)(b * 64 + jt)) * 8192;
            const float4* kh = (const float4*)(g_kh8 + gb);
            const float4* kl = (const float4*)(g_kl8 + gb);
            const float4* vh = (const float4*)(g_vh8 + gb);
            const float4* vl = (const float4*)(g_vl8 + gb);
            #pragma unroll
            for (int t = 0; t < 4; t++) {
                ((float4*)KH)[tid + t * 128]    = kh[tid + t * 128];
                ((float4*)KL)[tid + t * 128]    = kl[tid + t * 128];
                ((float4*)VH[s])[tid + t * 128] = vh[tid + t * 128];
                ((float4*)VL[s])[tid + t * 128] = vl[tid + t * 128];
            }
        }
        __syncthreads();

        // ---- S = Q^T K (issue first) ----
        float S[8][4];
        #pragma unroll
        for (int t = 0; t < 8; t++)
            #pragma unroll
            for (int k = 0; k < 4; k++) S[t][k] = 0.f;

        #pragma unroll
        for (int kc = 0; kc < 4; kc++) {
            #pragma unroll
            for (int jp = 0; jp < 4; jp++) {
                uint32_t off = sw128(
                    (uint32_t)((16 * jp + brow) * 128 + (kc * 16 + bcol) * 2));
                uint32_t k0, k1, k2, k3;
                ldsm4(k0, k1, k2, k3, kbH + off);
                mma16816(S[2 * jp],     qh[kc], k0, k1);
                mma16816(S[2 * jp + 1], qh[kc], k2, k3);
                mma16816(S[2 * jp],     ql[kc], k0, k1);
                mma16816(S[2 * jp + 1], ql[kc], k2, k3);
                ldsm4(k0, k1, k2, k3, kbL + off);
                mma16816(S[2 * jp],     qh[kc], k0, k1);
                mma16816(S[2 * jp + 1], qh[kc], k2, k3);
            }
        }

        // ---- deferred O += P_{j-1} V_{j-1} (overlaps softmax below) ----
        if (jt) {
            const int ps = (jt - 1) & 1;
            pv_gemm(O, pah, pal, smem_u32(VH[ps]), smem_u32(VL[ps]), brow, bcol);
        }

        // ---- online softmax on S_j (waits on S regs; O MMAs keep draining) ----
        float mx0 = -1e30f, mx1 = -1e30f;
        #pragma unroll
        for (int t = 0; t < 8; t++) {
            mx0 = fmaxf(mx0, fmaxf(S[t][0], S[t][1]));
            mx1 = fmaxf(mx1, fmaxf(S[t][2], S[t][3]));
        }
        mx0 = fmaxf(mx0, __shfl_xor_sync(0xffffffffu, mx0, 1));
        mx0 = fmaxf(mx0, __shfl_xor_sync(0xffffffffu, mx0, 2));
        mx1 = fmaxf(mx1, __shfl_xor_sync(0xffffffffu, mx1, 1));
        mx1 = fmaxf(mx1, __shfl_xor_sync(0xffffffffu, mx1, 2));
        const float mn0 = fmaxf(m0, mx0);
        const float mn1 = fmaxf(m1, mx1);
        const float sc0 = __expf(m0 - mn0);
        const float sc1 = __expf(m1 - mn1);
        m0 = mn0; m1 = mn1;

        float rs0 = 0.f, rs1 = 0.f;
        #pragma unroll
        for (int kc2 = 0; kc2 < 4; kc2++) {
            const int t0 = 2 * kc2, t1 = 2 * kc2 + 1;
            float p00 = __expf(S[t0][0] - mn0), p01 = __expf(S[t0][1] - mn0);
            float p02 = __expf(S[t0][2] - mn1), p03 = __expf(S[t0][3] - mn1);
            float p10 = __expf(S[t1][0] - mn0), p11 = __expf(S[t1][1] - mn0);
            float p12 = __expf(S[t1][2] - mn1), p13 = __expf(S[t1][3] - mn1);
            rs0 += (p00 + p01) + (p10 + p11);
            rs1 += (p02 + p03) + (p12 + p13);
            __half h00 = __float2half_rn(p00), h01 = __float2half_rn(p01);
            __half h02 = __float2half_rn(p02), h03 = __float2half_rn(p03);
            __half h10 = __float2half_rn(p10), h11 = __float2half_rn(p11);
            __half h12 = __float2half_rn(p12), h13 = __float2half_rn(p13);
            float q00 = p00 - __half2float(h00), q01 = p01 - __half2float(h01);
            float q02 = p02 - __half2float(h02), q03 = p03 - __half2float(h03);
            float q10 = p10 - __half2float(h10), q11 = p11 - __half2float(h11);
            float q12 = p12 - __half2float(h12), q13 = p13 - __half2float(h13);
            pah[kc2][0] = hpack(h00, h01);
            pah[kc2][1] = hpack(h02, h03);
            pah[kc2][2] = hpack(h10, h11);
            pah[kc2][3] = hpack(h12, h13);
            pal[kc2][0] = hpack(__float2half_rn(q00), __float2half_rn(q01));
            pal[kc2][1] = hpack(__float2half_rn(q02), __float2half_rn(q03));
            pal[kc2][2] = hpack(__float2half_rn(q10), __float2half_rn(q11));
            pal[kc2][3] = hpack(__float2half_rn(q12), __float2half_rn(q13));
        }
        rs0 += __shfl_xor_sync(0xffffffffu, rs0, 1);
        rs0 += __shfl_xor_sync(0xffffffffu, rs0, 2);
        rs1 += __shfl_xor_sync(0xffffffffu, rs1, 1);
        rs1 += __shfl_xor_sync(0xffffffffu, rs1, 2);
        l0 = l0 * sc0 + rs0;
        l1 = l1 * sc1 + rs1;

        // rescale O AFTER this iter's O-MMAs (reg deps), BEFORE next iter's
        #pragma unroll
        for (int t = 0; t < 8; t++) {
            O[t][0] *= sc0; O[t][1] *= sc0;
            O[t][2] *= sc1; O[t][3] *= sc1;
        }
    }

    // ---- flush last P tile (V stage 63&1 = 1 still resident) ----
    pv_gemm(O, pah, pal, smem_u32(VH[1]), smem_u32(VL[1]), brow, bcol);

    // ---- epilogue: normalize + store [b][d][n] ----
    const float inv0 = 1.f / l0;
    const float inv1 = 1.f / l1;
    const int r  = l >> 2;
    const int c0 = (l & 3) * 2;
    const int ng = it * 64 + 16 * w;
    #pragma unroll
    for (int t = 0; t < 8; t++) {
        int d = 8 * t + c0;
        g_ao[((size_t)(b * DIM + d))     * NPIX + ng + r]     = O[t][0] * inv0;
        g_ao[((size_t)(b * DIM + d + 1)) * NPIX + ng + r]     = O[t][1] * inv0;
        g_ao[((size_t)(b * DIM + d))     * NPIX + ng + r + 8] = O[t][2] * inv1;
        g_ao[((size_t)(b * DIM + d + 1)) * NPIX + ng + r + 8] = O[t][3] * inv1;
    }
}

// ============================================================================
// Kernel 4: out = LayerNorm_c( gamma*x + (w_out @ ao + b_out) )
// ============================================================================
__global__ __launch_bounds__(256) void k_out_ln(
    const float* __restrict__ x,
    const float* __restrict__ b_out, const float* __restrict__ gamma,
    const float* __restrict__ ln_w, const float* __restrict__ ln_b,
    float* __restrict__ out)
{
    __shared__ float aos[DIM * 16];
    __shared__ float xs[CIN * 17];
    __shared__ float red1[8 * 16];
    __shared__ float red2[8 * 16];
    __shared__ float mus[16], rstds[16];

    const int blk = blockIdx.x;
    const int b  = blk >> 8;
    const int n0 = (blk & 255) * 16;
    const int c  = threadIdx.x;

    #pragma unroll
    for (int t = 0; t < 4; t++) {
        int idx = c + t * 256;
        int d = idx >> 4, p = idx & 15;
        aos[idx] = g_ao[((b * DIM) + d) * NPIX + n0 + p];
    }
    #pragma unroll
    for (int t = 0; t < 4; t++) {
        int idx4 = c + t * 256;
        int ch = idx4 >> 2, p4 = idx4 & 3;
        float4 v = *(const float4*)&x[((b * CIN) + ch) * NPIX + n0 + p4 * 4];
        xs[ch * 17 + p4 * 4 + 0] = v.x;
        xs[ch * 17 + p4 * 4 + 1] = v.y;
        xs[ch * 17 + p4 * 4 + 2] = v.z;
        xs[ch * 17 + p4 * 4 + 3] = v.w;
    }
    const float g0 = gamma[0];
    const float bo = b_out[c];
    __syncthreads();

    float tv[16];
    #pragma unroll
    for (int p = 0; p < 16; p++) tv[p] = bo;
    #pragma unroll 16
    for (int d = 0; d < 64; d++) {
        float wd = __ldg(&g_wt[d * CIN + c]);
        #pragma unroll
        for (int p = 0; p < 16; p++) tv[p] += wd * aos[d * 16 + p];
    }
    #pragma unroll
    for (int p = 0; p < 16; p++) tv[p] += g0 * xs[c * 17 + p];

    const int warp = c >> 5, lane = c & 31;
    #pragma unroll
    for (int p = 0; p < 16; p++) {
        float s1 = tv[p], s2 = tv[p] * tv[p];
        #pragma unroll
        for (int off = 16; off > 0; off >>= 1) {
            s1 += __shfl_xor_sync(0xffffffffu, s1, off);
            s2 += __shfl_xor_sync(0xffffffffu, s2, off);
        }
        if (lane == 0) { red1[warp * 16 + p] = s1; red2[warp * 16 + p] = s2; }
    }
    __syncthreads();
    if (c < 16) {
        float s1 = 0.f, s2 = 0.f;
        #pragma unroll
        for (int w = 0; w < 8; w++) { s1 += red1[w * 16 + c]; s2 += red2[w * 16 + c]; }
        float mu  = s1 * (1.f / 256.f);
        float var = s2 * (1.f / 256.f) - mu * mu;
        mus[c] = mu;
        rstds[c] = rsqrtf(var + LN_EPS);
    }
    __syncthreads();

    const float lw = ln_w[c], lb = ln_b[c];
    #pragma unroll
    for (int p = 0; p < 16; p++)
        xs[c * 17 + p] = (tv[p] - mus[p]) * rstds[p] * lw + lb;
    __syncthreads();

    #pragma unroll
    for (int t = 0; t < 4; t++) {
        int idx4 = c + t * 256;
        int ch = idx4 >> 2, p4 = idx4 & 3;
        float4 o4 = make_float4(xs[ch * 17 + p4 * 4 + 0],
                                xs[ch * 17 + p4 * 4 + 1],
                                xs[ch * 17 + p4 * 4 + 2],
                                xs[ch * 17 + p4 * 4 + 3]);
        *(float4*)&out[((b * CIN) + ch) * NPIX + n0 + p4 * 4] = o4;
    }
}

// ============================================================================
extern "C" void kernel_launch(void* const* d_in, const int* in_sizes, int n_in,
                              void* d_out, int out_size)
{
    const float* x     = (const float*)d_in[0];
    const float* w_in  = (const float*)d_in[1];
    const float* b_in  = (const float*)d_in[2];
    const float* wq    = (const float*)d_in[3];
    const float* bq    = (const float*)d_in[4];
    const float* wk    = (const float*)d_in[5];
    const float* bk    = (const float*)d_in[6];
    const float* wv    = (const float*)d_in[7];
    const float* bv    = (const float*)d_in[8];
    const float* w_out = (const float*)d_in[9];
    const float* b_out = (const float*)d_in[10];
    const float* gamma = (const float*)d_in[11];
    const float* ln_w  = (const float*)d_in[12];
    const float* ln_b  = (const float*)d_in[13];
    float* out = (float*)d_out;

    k_transpose_w<<<DIM, CIN>>>(w_out);
    k_proj_in<<<dim3(64, BATCH), 256>>>(x, w_in, b_in);
    k_qkv<<<dim3(64, BATCH, 3), 256>>>(wq, bq, wk, bk, wv, bv);
    k_flash_mma<<<dim3(64, BATCH), 128>>>();
    k_out_ln<<<BATCH * 256, 256>>>(x, b_out, gamma, ln_w, ln_b, out);
}

// round 17
// speedup vs baseline: 1.0714x; 1.0714x over previous
#include <cuda_runtime.h>
#include <cuda_fp16.h>
#include <cstdint>

#define BATCH 4
#define CIN   256
#define DIM   64
#define HWDIM 64
#define NPIX  4096
#define LN_EPS 1e-5f

// ---------------- scratch (device globals; no allocation allowed) ----------
__device__ float g_att[BATCH * DIM * NPIX];   // inner projection out [b][d][n]
__device__ float g_ao [BATCH * DIM * NPIX];   // attention out [b][d][n]
__device__ float g_wt [DIM * CIN];            // w_out transposed [d][c]

// fp16 hi/lo staging, PRE-SWIZZLED (SW128-style) 8KB tiles (64x64 halfs):
// Q: tile it=n>>6, byte sw128((n&63)*128 + d*2)   [row][d]
// K: tile jt=n>>6, byte sw128((n&63)*128 + d*2)   [key][d]
// V: tile jt=n>>6, byte sw128(d*128 + (n&63)*2)   [d][key]
__device__ __align__(16) unsigned char g_qh8[BATCH * 64 * 8192];
__device__ __align__(16) unsigned char g_ql8[BATCH * 64 * 8192];
__device__ __align__(16) unsigned char g_kh8[BATCH * 64 * 8192];
__device__ __align__(16) unsigned char g_kl8[BATCH * 64 * 8192];
__device__ __align__(16) unsigned char g_vh8[BATCH * 64 * 8192];
__device__ __align__(16) unsigned char g_vl8[BATCH * 64 * 8192];

// ---------------- helpers --------------------------------------------------
__device__ __forceinline__ uint32_t smem_u32(const void* p) {
    uint32_t a;
    asm("{ .reg .u64 t; cvta.to.shared.u64 t, %1; cvt.u32.u64 %0, t; }"
        : "=r"(a) : "l"(p));
    return a;
}
__device__ __forceinline__ uint32_t sw128(uint32_t off) {
    return off ^ ((off >> 3) & 0x70);
}
__device__ __forceinline__ void ldsm4(uint32_t& r0, uint32_t& r1,
                                      uint32_t& r2, uint32_t& r3, uint32_t addr) {
    asm volatile("ldmatrix.sync.aligned.m8n8.x4.shared.b16 {%0,%1,%2,%3}, [%4];"
        : "=r"(r0), "=r"(r1), "=r"(r2), "=r"(r3) : "r"(addr));
}
__device__ __forceinline__ void mma16816(float* d, const uint32_t* a,
                                         uint32_t b0, uint32_t b1) {
    asm volatile(
        "mma.sync.aligned.m16n8k16.row.col.f32.f16.f16.f32 "
        "{%0,%1,%2,%3}, {%4,%5,%6,%7}, {%8,%9}, {%0,%1,%2,%3};"
        : "+f"(d[0]), "+f"(d[1]), "+f"(d[2]), "+f"(d[3])
        : "r"(a[0]), "r"(a[1]), "r"(a[2]), "r"(a[3]), "r"(b0), "r"(b1));
}
__device__ __forceinline__ uint32_t hpack(__half a, __half b) {
    return (uint32_t)__half_as_ushort(a) | ((uint32_t)__half_as_ushort(b) << 16);
}
__device__ __forceinline__ void cp16(uint32_t dst, const void* src) {
    asm volatile("cp.async.cg.shared.global [%0], [%1], 16;"
                 :: "r"(dst), "l"(src) : "memory");
}
#define CP_COMMIT() asm volatile("cp.async.commit_group;" ::: "memory")
#define CP_WAIT0()  asm volatile("cp.async.wait_group 0;" ::: "memory")

// ============================================================================
// Kernel 0: transpose w_out [c][d] -> g_wt [d][c]
// ============================================================================
__global__ __launch_bounds__(256) void k_transpose_w(const float* __restrict__ w_out)
{
    g_wt[blockIdx.x * CIN + threadIdx.x] = w_out[threadIdx.x * DIM + blockIdx.x];
}

// ============================================================================
// Kernel 1: 1x1 in-projection (plain FFMA, proven)
// ============================================================================
__global__ __launch_bounds__(256) void k_proj_in(
    const float* __restrict__ x, const float* __restrict__ w,
    const float* __restrict__ bias)
{
    __shared__ float ws[32 * 68];
    __shared__ float xs[32 * 68];
    const int b   = blockIdx.y;
    const int n0  = blockIdx.x * 64;
    const int tid = threadIdx.x;
    const int ti  = tid >> 4;
    const int tj  = tid & 15;

    float acc[4][4] = {};
    for (int c0 = 0; c0 < CIN; c0 += 32) {
        __syncthreads();
        #pragma unroll
        for (int t = 0; t < 8; t++) {
            int idx = tid + t * 256;
            int d = idx >> 5, ci = idx & 31;
            ws[ci * 68 + d] = w[d * CIN + c0 + ci];
        }
        #pragma unroll
        for (int t = 0; t < 2; t++) {
            int idx4 = tid + t * 256;
            int ci = idx4 >> 4, p4 = idx4 & 15;
            float4 v = *(const float4*)&x[((b * CIN) + c0 + ci) * NPIX + n0 + p4 * 4];
            *(float4*)&xs[ci * 68 + p4 * 4] = v;
        }
        __syncthreads();
        #pragma unroll
        for (int ci = 0; ci < 32; ci++) {
            float4 a4 = *(const float4*)&ws[ci * 68 + 4 * ti];
            float4 b4 = *(const float4*)&xs[ci * 68 + 4 * tj];
            acc[0][0] += a4.x * b4.x; acc[0][1] += a4.x * b4.y;
            acc[0][2] += a4.x * b4.z; acc[0][3] += a4.x * b4.w;
            acc[1][0] += a4.y * b4.x; acc[1][1] += a4.y * b4.y;
            acc[1][2] += a4.y * b4.z; acc[1][3] += a4.y * b4.w;
            acc[2][0] += a4.z * b4.x; acc[2][1] += a4.z * b4.y;
            acc[2][2] += a4.z * b4.z; acc[2][3] += a4.z * b4.w;
            acc[3][0] += a4.w * b4.x; acc[3][1] += a4.w * b4.y;
            acc[3][2] += a4.w * b4.z; acc[3][3] += a4.w * b4.w;
        }
    }
    #pragma unroll
    for (int di = 0; di < 4; di++) {
        int d = 4 * ti + di;
        float bb = bias[d];
        float4 o = make_float4(acc[di][0] + bb, acc[di][1] + bb,
                               acc[di][2] + bb, acc[di][3] + bb);
        *(float4*)&g_att[((b * DIM) + d) * NPIX + n0 + 4 * tj] = o;
    }
}

// ============================================================================
// Kernel 2: 3x3 conv (pad 1) -> fp16 hi/lo pre-swizzled 64x64 tiles
// ============================================================================
__global__ __launch_bounds__(256) void k_qkv(
    const float* __restrict__ wq, const float* __restrict__ bq,
    const float* __restrict__ wk, const float* __restrict__ bk,
    const float* __restrict__ wv, const float* __restrict__ bv)
{
    __shared__ float att_s[DIM * 100];
    __shared__ float ws[8 * 64 * 9];

    const int b = blockIdx.y;
    const int z = blockIdx.z;
    const float* w    = (z == 0) ? wq : (z == 1) ? wk : wv;
    const float* bias = (z == 0) ? bq : (z == 1) ? bk : bv;

    const int tile = blockIdx.x;
    const int th = (tile >> 3) * 8, tw = (tile & 7) * 8;
    const int tid = threadIdx.x;

    for (int idx = tid; idx < DIM * 100; idx += 256) {
        int c = idx / 100, rem = idx - c * 100;
        int r = rem / 10, cc = rem - r * 10;
        int gh = th - 1 + r, gw = tw - 1 + cc;
        float v = 0.f;
        if (gh >= 0 && gh < HWDIM && gw >= 0 && gw < HWDIM)
            v = g_att[((b * DIM) + c) * NPIX + gh * HWDIM + gw];
        att_s[idx] = v;
    }

    const int d  = tid & 63;
    const int sub = tid >> 6;
    const int sy = (sub >> 1) * 4, sx = (sub & 1) * 4;
    float acc[16] = {};

    for (int c8 = 0; c8 < 8; c8++) {
        __syncthreads();
        #pragma unroll
        for (int t = 0; t < 18; t++) {
            int idx = tid + t * 256;
            int ci = idx / 576, rem2 = idx - ci * 576;
            int dd = rem2 / 9, k = rem2 - dd * 9;
            ws[idx] = w[(dd * DIM + c8 * 8 + ci) * 9 + k];
        }
        __syncthreads();
        #pragma unroll
        for (int ci = 0; ci < 8; ci++) {
            int c = c8 * 8 + ci;
            float patch[36];
            #pragma unroll
            for (int ry = 0; ry < 6; ry++)
                #pragma unroll
                for (int rx = 0; rx < 6; rx++)
                    patch[ry * 6 + rx] = att_s[c * 100 + (sy + ry) * 10 + sx + rx];
            const float* wp = &ws[(ci * 64 + d) * 9];
            float w9[9];
            #pragma unroll
            for (int k = 0; k < 9; k++) w9[k] = wp[k];
            #pragma unroll
            for (int py = 0; py < 4; py++)
                #pragma unroll
                for (int px = 0; px < 4; px++) {
                    float a = acc[py * 4 + px];
                    #pragma unroll
                    for (int ky = 0; ky < 3; ky++)
                        #pragma unroll
                        for (int kx = 0; kx < 3; kx++)
                            a += w9[ky * 3 + kx] * patch[(py + ky) * 6 + px + kx];
                    acc[py * 4 + px] = a;
                }
        }
    }

    const float bb = bias[d];
    #pragma unroll
    for (int py = 0; py < 4; py++)
        #pragma unroll
        for (int px = 0; px < 4; px++) {
            float val = acc[py * 4 + px] + bb;
            int n = (th + sy + py) * HWDIM + tw + sx + px;
            __half hi = __float2half_rn(val);
            __half lo = __float2half_rn(val - __half2float(hi));
            int t = n >> 6, r = n & 63;
            size_t tbase = ((size_t)(b * 64 + t)) * 8192;
            if (z == 0) {
                uint32_t off = sw128((uint32_t)(r * 128 + d * 2));
                *(__half*)(g_qh8 + tbase + off) = hi;
                *(__half*)(g_ql8 + tbase + off) = lo;
            } else if (z == 1) {
                uint32_t off = sw128((uint32_t)(r * 128 + d * 2));
                *(__half*)(g_kh8 + tbase + off) = hi;
                *(__half*)(g_kl8 + tbase + off) = lo;
            } else {
                uint32_t off = sw128((uint32_t)(d * 128 + r * 2));
                *(__half*)(g_vh8 + tbase + off) = hi;
                *(__half*)(g_vl8 + tbase + off) = lo;
            }
        }
}

// ============================================================================
// Kernel 3: flash attention via mma.sync (fp16 hi/lo, f32 accumulate).
// Round-13 compute structure (proven fastest) + cp.async DOUBLE-BUFFERED K/V:
// stage s = 32KB (KH|KL|VH|VL @ 8KB each); at iter jt: wait stage jt (was
// prefetched during iter jt-1), barrier, prefetch jt+1 into the other stage,
// then compute. One outstanding cp.async group at a time.
// 64KB dynamic smem.
// ============================================================================
__global__ __launch_bounds__(128) void k_flash_mma()
{
    extern __shared__ __align__(128) unsigned char dsm[];

    const int tid = threadIdx.x;
    const int w   = tid >> 5;
    const int l   = tid & 31;
    const int b   = blockIdx.y;
    const int it  = blockIdx.x;

    const uint32_t sb_u32 = smem_u32(dsm);

    // ---- prefetch stage 0 (jt=0) immediately ----
    {
        size_t gb = ((size_t)(b * 64 + 0)) * 8192;
        #pragma unroll
        for (int t = 0; t < 4; t++) {
            uint32_t off = (uint32_t)(tid + t * 128) * 16;
            cp16(sb_u32 + off,         g_kh8 + gb + off);
            cp16(sb_u32 + 8192 + off,  g_kl8 + gb + off);
            cp16(sb_u32 + 16384 + off, g_vh8 + gb + off);
            cp16(sb_u32 + 24576 + off, g_vl8 + gb + off);
        }
        CP_COMMIT();
    }

    // ---- stage Q tile (hi/lo) through stage-1 buffer while stage 0 loads ----
    {
        const float4* sh = (const float4*)(g_qh8 + ((size_t)(b * 64 + it)) * 8192);
        const float4* sl = (const float4*)(g_ql8 + ((size_t)(b * 64 + it)) * 8192);
        float4* dh = (float4*)(dsm + 32768);
        float4* dl = (float4*)(dsm + 32768 + 8192);
        #pragma unroll
        for (int t = 0; t < 4; t++) {
            dh[tid + t * 128] = sh[tid + t * 128];
            dl[tid + t * 128] = sl[tid + t * 128];
        }
    }
    __syncthreads();

    // ---- persistent Q A-frags (4 k-chunks x hi/lo) ----
    uint32_t qh[4][4], ql[4][4];
    {
        const uint32_t qbH = sb_u32 + 32768, qbL = sb_u32 + 32768 + 8192;
        int row  = 16 * w + (l & 15);
        int colb = (l >> 4) << 3;
        #pragma unroll
        for (int kc = 0; kc < 4; kc++) {
            uint32_t off = sw128((uint32_t)(row * 128 + (kc * 16 + colb) * 2));
            ldsm4(qh[kc][0], qh[kc][1], qh[kc][2], qh[kc][3], qbH + off);
            ldsm4(ql[kc][0], ql[kc][1], ql[kc][2], ql[kc][3], qbL + off);
        }
    }
    __syncthreads();   // all Q reads done before jt=1 prefetch overwrites stage 1

    const int brow = ((l >> 4) << 3) + (l & 7);
    const int bcol = (l & 8);

    float O[8][4];
    #pragma unroll
    for (int t = 0; t < 8; t++)
        #pragma unroll
        for (int k = 0; k < 4; k++) O[t][k] = 0.f;
    float m0 = -1e30f, m1 = -1e30f, l0 = 0.f, l1 = 0.f;

    for (int jt = 0; jt < 64; jt++) {
        const uint32_t stg = sb_u32 + (uint32_t)(jt & 1) * 32768;

        CP_WAIT0();        // stage jt resident
        __syncthreads();   // visible to all warps; prior iter fully done

        if (jt < 63) {     // prefetch jt+1 into the other stage
            size_t gb = ((size_t)(b * 64 + jt + 1)) * 8192;
            uint32_t dst = sb_u32 + (uint32_t)((jt + 1) & 1) * 32768;
            #pragma unroll
            for (int t = 0; t < 4; t++) {
                uint32_t off = (uint32_t)(tid + t * 128) * 16;
                cp16(dst + off,         g_kh8 + gb + off);
                cp16(dst + 8192 + off,  g_kl8 + gb + off);
                cp16(dst + 16384 + off, g_vh8 + gb + off);
                cp16(dst + 24576 + off, g_vl8 + gb + off);
            }
            CP_COMMIT();
        }

        const uint32_t kbH = stg, kbL = stg + 8192;
        const uint32_t vbH = stg + 16384, vbL = stg + 24576;

        // ---- S = Q^T K (16 x 64 per warp) ----
        float S[8][4];
        #pragma unroll
        for (int t = 0; t < 8; t++)
            #pragma unroll
            for (int k = 0; k < 4; k++) S[t][k] = 0.f;

        #pragma unroll
        for (int kc = 0; kc < 4; kc++) {
            #pragma unroll
            for (int jp = 0; jp < 4; jp++) {
                uint32_t off = sw128(
                    (uint32_t)((16 * jp + brow) * 128 + (kc * 16 + bcol) * 2));
                uint32_t k0, k1, k2, k3;
                ldsm4(k0, k1, k2, k3, kbH + off);
                mma16816(S[2 * jp],     qh[kc], k0, k1);
                mma16816(S[2 * jp + 1], qh[kc], k2, k3);
                mma16816(S[2 * jp],     ql[kc], k0, k1);
                mma16816(S[2 * jp + 1], ql[kc], k2, k3);
                ldsm4(k0, k1, k2, k3, kbL + off);
                mma16816(S[2 * jp],     qh[kc], k0, k1);
                mma16816(S[2 * jp + 1], qh[kc], k2, k3);
            }
        }

        // ---- online softmax (rows r = l>>2 and r+8) ----
        float mx0 = -1e30f, mx1 = -1e30f;
        #pragma unroll
        for (int t = 0; t < 8; t++) {
            mx0 = fmaxf(mx0, fmaxf(S[t][0], S[t][1]));
            mx1 = fmaxf(mx1, fmaxf(S[t][2], S[t][3]));
        }
        mx0 = fmaxf(mx0, __shfl_xor_sync(0xffffffffu, mx0, 1));
        mx0 = fmaxf(mx0, __shfl_xor_sync(0xffffffffu, mx0, 2));
        mx1 = fmaxf(mx1, __shfl_xor_sync(0xffffffffu, mx1, 1));
        mx1 = fmaxf(mx1, __shfl_xor_sync(0xffffffffu, mx1, 2));
        const float mn0 = fmaxf(m0, mx0);
        const float mn1 = fmaxf(m1, mx1);
        const float sc0 = __expf(m0 - mn0);
        const float sc1 = __expf(m1 - mn1);
        m0 = mn0; m1 = mn1;

        uint32_t pah[4][4], pal[4][4];
        float rs0 = 0.f, rs1 = 0.f;
        #pragma unroll
        for (int kc2 = 0; kc2 < 4; kc2++) {
            const int t0 = 2 * kc2, t1 = 2 * kc2 + 1;
            float p00 = __expf(S[t0][0] - mn0), p01 = __expf(S[t0][1] - mn0);
            float p02 = __expf(S[t0][2] - mn1), p03 = __expf(S[t0][3] - mn1);
            float p10 = __expf(S[t1][0] - mn0), p11 = __expf(S[t1][1] - mn0);
            float p12 = __expf(S[t1][2] - mn1), p13 = __expf(S[t1][3] - mn1);
            rs0 += (p00 + p01) + (p10 + p11);
            rs1 += (p02 + p03) + (p12 + p13);
            __half h00 = __float2half_rn(p00), h01 = __float2half_rn(p01);
            __half h02 = __float2half_rn(p02), h03 = __float2half_rn(p03);
            __half h10 = __float2half_rn(p10), h11 = __float2half_rn(p11);
            __half h12 = __float2half_rn(p12), h13 = __float2half_rn(p13);
            float q00 = p00 - __half2float(h00), q01 = p01 - __half2float(h01);
            float q02 = p02 - __half2float(h02), q03 = p03 - __half2float(h03);
            float q10 = p10 - __half2float(h10), q11 = p11 - __half2float(h11);
            float q12 = p12 - __half2float(h12), q13 = p13 - __half2float(h13);
            pah[kc2][0] = hpack(h00, h01);
            pah[kc2][1] = hpack(h02, h03);
            pah[kc2][2] = hpack(h10, h11);
            pah[kc2][3] = hpack(h12, h13);
            pal[kc2][0] = hpack(__float2half_rn(q00), __float2half_rn(q01));
            pal[kc2][1] = hpack(__float2half_rn(q02), __float2half_rn(q03));
            pal[kc2][2] = hpack(__float2half_rn(q10), __float2half_rn(q11));
            pal[kc2][3] = hpack(__float2half_rn(q12), __float2half_rn(q13));
        }
        rs0 += __shfl_xor_sync(0xffffffffu, rs0, 1);
        rs0 += __shfl_xor_sync(0xffffffffu, rs0, 2);
        rs1 += __shfl_xor_sync(0xffffffffu, rs1, 1);
        rs1 += __shfl_xor_sync(0xffffffffu, rs1, 2);
        l0 = l0 * sc0 + rs0;
        l1 = l1 * sc1 + rs1;

        #pragma unroll
        for (int t = 0; t < 8; t++) {
            O[t][0] *= sc0; O[t][1] *= sc0;
            O[t][2] *= sc1; O[t][3] *= sc1;
        }

        // ---- O += P * V ----
        #pragma unroll
        for (int kc2 = 0; kc2 < 4; kc2++) {
            #pragma unroll
            for (int dp = 0; dp < 4; dp++) {
                uint32_t off = sw128(
                    (uint32_t)((16 * dp + brow) * 128 + (kc2 * 16 + bcol) * 2));
                uint32_t v0, v1, v2, v3;
                ldsm4(v0, v1, v2, v3, vbH + off);
                mma16816(O[2 * dp],     pah[kc2], v0, v1);
                mma16816(O[2 * dp + 1], pah[kc2], v2, v3);
                mma16816(O[2 * dp],     pal[kc2], v0, v1);
                mma16816(O[2 * dp + 1], pal[kc2], v2, v3);
                ldsm4(v0, v1, v2, v3, vbL + off);
                mma16816(O[2 * dp],     pah[kc2], v0, v1);
                mma16816(O[2 * dp + 1], pah[kc2], v2, v3);
            }
        }
    }

    // ---- epilogue: normalize + store [b][d][n] ----
    const float inv0 = 1.f / l0;
    const float inv1 = 1.f / l1;
    const int r  = l >> 2;
    const int c0 = (l & 3) * 2;
    const int ng = it * 64 + 16 * w;
    #pragma unroll
    for (int t = 0; t < 8; t++) {
        int d = 8 * t + c0;
        g_ao[((size_t)(b * DIM + d))     * NPIX + ng + r]     = O[t][0] * inv0;
        g_ao[((size_t)(b * DIM + d + 1)) * NPIX + ng + r]     = O[t][1] * inv0;
        g_ao[((size_t)(b * DIM + d))     * NPIX + ng + r + 8] = O[t][2] * inv1;
        g_ao[((size_t)(b * DIM + d + 1)) * NPIX + ng + r + 8] = O[t][3] * inv1;
    }
}

// ============================================================================
// Kernel 4: out = LayerNorm_c( gamma*x + (w_out @ ao + b_out) )
// ============================================================================
__global__ __launch_bounds__(256) void k_out_ln(
    const float* __restrict__ x,
    const float* __restrict__ b_out, const float* __restrict__ gamma,
    const float* __restrict__ ln_w, const float* __restrict__ ln_b,
    float* __restrict__ out)
{
    __shared__ float aos[DIM * 16];
    __shared__ float xs[CIN * 17];
    __shared__ float red1[8 * 16];
    __shared__ float red2[8 * 16];
    __shared__ float mus[16], rstds[16];

    const int blk = blockIdx.x;
    const int b  = blk >> 8;
    const int n0 = (blk & 255) * 16;
    const int c  = threadIdx.x;

    #pragma unroll
    for (int t = 0; t < 4; t++) {
        int idx = c + t * 256;
        int d = idx >> 4, p = idx & 15;
        aos[idx] = g_ao[((b * DIM) + d) * NPIX + n0 + p];
    }
    #pragma unroll
    for (int t = 0; t < 4; t++) {
        int idx4 = c + t * 256;
        int ch = idx4 >> 2, p4 = idx4 & 3;
        float4 v = *(const float4*)&x[((b * CIN) + ch) * NPIX + n0 + p4 * 4];
        xs[ch * 17 + p4 * 4 + 0] = v.x;
        xs[ch * 17 + p4 * 4 + 1] = v.y;
        xs[ch * 17 + p4 * 4 + 2] = v.z;
        xs[ch * 17 + p4 * 4 + 3] = v.w;
    }
    const float g0 = gamma[0];
    const float bo = b_out[c];
    __syncthreads();

    float tv[16];
    #pragma unroll
    for (int p = 0; p < 16; p++) tv[p] = bo;
    #pragma unroll 16
    for (int d = 0; d < 64; d++) {
        float wd = __ldg(&g_wt[d * CIN + c]);
        #pragma unroll
        for (int p = 0; p < 16; p++) tv[p] += wd * aos[d * 16 + p];
    }
    #pragma unroll
    for (int p = 0; p < 16; p++) tv[p] += g0 * xs[c * 17 + p];

    const int warp = c >> 5, lane = c & 31;
    #pragma unroll
    for (int p = 0; p < 16; p++) {
        float s1 = tv[p], s2 = tv[p] * tv[p];
        #pragma unroll
        for (int off = 16; off > 0; off >>= 1) {
            s1 += __shfl_xor_sync(0xffffffffu, s1, off);
            s2 += __shfl_xor_sync(0xffffffffu, s2, off);
        }
        if (lane == 0) { red1[warp * 16 + p] = s1; red2[warp * 16 + p] = s2; }
    }
    __syncthreads();
    if (c < 16) {
        float s1 = 0.f, s2 = 0.f;
        #pragma unroll
        for (int w = 0; w < 8; w++) { s1 += red1[w * 16 + c]; s2 += red2[w * 16 + c]; }
        float mu  = s1 * (1.f / 256.f);
        float var = s2 * (1.f / 256.f) - mu * mu;
        mus[c] = mu;
        rstds[c] = rsqrtf(var + LN_EPS);
    }
    __syncthreads();

    const float lw = ln_w[c], lb = ln_b[c];
    #pragma unroll
    for (int p = 0; p < 16; p++)
        xs[c * 17 + p] = (tv[p] - mus[p]) * rstds[p] * lw + lb;
    __syncthreads();

    #pragma unroll
    for (int t = 0; t < 4; t++) {
        int idx4 = c + t * 256;
        int ch = idx4 >> 2, p4 = idx4 & 3;
        float4 o4 = make_float4(xs[ch * 17 + p4 * 4 + 0],
                                xs[ch * 17 + p4 * 4 + 1],
                                xs[ch * 17 + p4 * 4 + 2],
                                xs[ch * 17 + p4 * 4 + 3]);
        *(float4*)&out[((b * CIN) + ch) * NPIX + n0 + p4 * 4] = o4;
    }
}

// ============================================================================
extern "C" void kernel_launch(void* const* d_in, const int* in_sizes, int n_in,
                              void* d_out, int out_size)
{
    const float* x     = (const float*)d_in[0];
    const float* w_in  = (const float*)d_in[1];
    const float* b_in  = (const float*)d_in[2];
    const float* wq    = (const float*)d_in[3];
    const float* bq    = (const float*)d_in[4];
    const float* wk    = (const float*)d_in[5];
    const float* bk    = (const float*)d_in[6];
    const float* wv    = (const float*)d_in[7];
    const float* bv    = (const float*)d_in[8];
    const float* w_out = (const float*)d_in[9];
    const float* b_out = (const float*)d_in[10];
    const float* gamma = (const float*)d_in[11];
    const float* ln_w  = (const float*)d_in[12];
    const float* ln_b  = (const float*)d_in[13];
    float* out = (float*)d_out;

    cudaFuncSetAttribute(k_flash_mma,
                         cudaFuncAttributeMaxDynamicSharedMemorySize, 65536);

    k_transpose_w<<<DIM, CIN>>>(w_out);
    k_proj_in<<<dim3(64, BATCH), 256>>>(x, w_in, b_in);
    k_qkv<<<dim3(64, BATCH, 3), 256>>>(wq, bq, wk, bk, wv, bv);
    k_flash_mma<<<dim3(64, BATCH), 128, 65536>>>();
    k_out_ln<<<BATCH * 256, 256>>>(x, b_out, gamma, ln_w, ln_b, out);
}